// round 1
// baseline (speedup 1.0000x reference)
#include <cuda_runtime.h>
#include <cstdint>
#include <cstring>
#include <cmath>

#define BB 64
#define HH 256
#define WW 256
#define IMGS 224
#define NPIX (IMGS*IMGS)   /* 50176 */
#define NBLK 196           /* 50176 / 256 */

// ---------------- device scratch (static globals; no allocs) ----------------
__device__ float         g_xw[BB*3*HH*WW];     // warped 256x256
__device__ unsigned char g_mask[BB*HH*WW];     // validity mask
__device__ float         g_xc[BB*3*NPIX];      // cropped 224x224
__device__ float         g_xj[BB*3*NPIX];      // after color jitter
__device__ float         g_partial[BB*NBLK];   // gray partial sums
__device__ float         g_mean[BB];           // gray means
__device__ int           g_crop[BB*3];         // x0,y0,s per batch

// ---------------- parameter structs (passed by value) ----------------
struct WarpP { float inv[BB][6]; };
struct CropP { float fb[BB]; };
struct JitP  { float fb[BB], fc[BB], fs[BB], fhue[BB]; int ap[BB]; };
struct BlurP { float ky[BB][3]; float kx[BB][9]; int ap[BB]; };

// ---------------- K1: affine warp + coverage mask ----------------
__global__ void warp_kernel(const float* __restrict__ x, WarpP P) {
    int idx = blockIdx.x * blockDim.x + threadIdx.x;
    if (idx >= BB*HH*WW) return;
    int b = idx >> 16;
    int p = idx & 65535;
    int h = p >> 8;
    int w = p & 255;
    const float* m = P.inv[b];
    float fx = (float)w, fy = (float)h;
    float sx = m[0]*fx + m[1]*fy + m[2];
    float sy = m[3]*fx + m[4]*fy + m[5];

    // coverage: bilinear of ones with zero border (unclamped coords)
    float x0f = floorf(sx), y0f = floorf(sy);
    int xi = (int)x0f, yi = (int)y0f;
    float wx = sx - x0f, wy = sy - y0f;
    float i00 = (yi   >= 0 && yi   < HH && xi   >= 0 && xi   < WW) ? 1.f : 0.f;
    float i01 = (yi   >= 0 && yi   < HH && xi+1 >= 0 && xi+1 < WW) ? 1.f : 0.f;
    float i10 = (yi+1 >= 0 && yi+1 < HH && xi   >= 0 && xi   < WW) ? 1.f : 0.f;
    float i11 = (yi+1 >= 0 && yi+1 < HH && xi+1 >= 0 && xi+1 < WW) ? 1.f : 0.f;
    float cov = i00*(1.f-wy)*(1.f-wx) + i01*(1.f-wy)*wx + i10*wy*(1.f-wx) + i11*wy*wx;
    g_mask[idx] = (cov > 0.5f) ? 1 : 0;

    // image sample with border clamp
    float cxs = fminf(fmaxf(sx, 0.f), 255.f);
    float cys = fminf(fmaxf(sy, 0.f), 255.f);
    float cx0f = floorf(cxs), cy0f = floorf(cys);
    int cx0 = (int)cx0f, cy0 = (int)cy0f;
    float cwx = cxs - cx0f, cwy = cys - cy0f;
    int x1 = min(cx0 + 1, 255), y1 = min(cy0 + 1, 255);
    float w00 = (1.f-cwy)*(1.f-cwx), w01 = (1.f-cwy)*cwx;
    float w10 = cwy*(1.f-cwx),       w11 = cwy*cwx;
    const float* xb = x + (size_t)b*3*HH*WW;
    float* ob = g_xw + (size_t)b*3*HH*WW;
    #pragma unroll
    for (int c = 0; c < 3; c++) {
        const float* img = xb + c*HH*WW;
        float v = img[cy0*WW + cx0]*w00 + img[cy0*WW + x1]*w01
                + img[y1*WW + cx0]*w10  + img[y1*WW + x1]*w11;
        ob[c*HH*WW + h*WW + w] = v;
    }
}

// ---------------- K2: per-batch max-square DP ----------------
__global__ void maxsq_kernel() {
    int b = blockIdx.x;
    int j = threadIdx.x;
    __shared__ int prev[256];
    __shared__ int wmin[8];
    prev[j] = 0;
    int bestv = 0, besti = 0;
    int allm = 1;
    const unsigned char* mb = g_mask + (size_t)b*HH*WW;
    int lane = j & 31, wd = j >> 5;
    __syncthreads();
    for (int i = 0; i < HH; i++) {
        int m = mb[i*WW + j];
        allm &= m;
        int pl = (j > 0) ? prev[j-1] : 0;
        int bj = min(prev[j], pl) + 1;
        int w = m ? bj : 0;
        int v = w - j;
        __syncthreads();
        int xv = v;
        #pragma unroll
        for (int o = 1; o < 32; o <<= 1) {
            int y = __shfl_up_sync(0xffffffffu, xv, o);
            if (lane >= o) xv = min(xv, y);
        }
        if (lane == 31) wmin[wd] = xv;
        __syncthreads();
        int off = 0x7fffffff;
        for (int t = 0; t < wd; t++) off = min(off, wmin[t]);
        int pm = min(xv, off);
        int dcur = min(j + 1, pm + j);
        prev[j] = dcur;
        if (dcur > bestv) { bestv = dcur; besti = i*WW + j; }
        __syncthreads();
    }
    __shared__ int sv[256], si[256];
    sv[j] = bestv; si[j] = besti;
    __syncthreads();
    for (int stride = 128; stride > 0; stride >>= 1) {
        if (j < stride) {
            int v2 = sv[j+stride], i2 = si[j+stride];
            if (v2 > sv[j] || (v2 == sv[j] && i2 < si[j])) { sv[j] = v2; si[j] = i2; }
        }
        __syncthreads();
    }
    int full = __syncthreads_and(allm);
    if (j == 0) {
        int s = sv[0], idx = si[0];
        int ii = idx >> 8, jj = idx & 255;
        int x0 = jj + 1 - s, y0 = ii + 1 - s;
        if (s == 0) { x0 = WW/2; y0 = HH/2; s = 1; }
        if (full)   { x0 = 0; y0 = 0; s = 256; }
        g_crop[b*3+0] = x0; g_crop[b*3+1] = y0; g_crop[b*3+2] = s;
    }
}

// ---------------- K3: crop resample + brightness-gray partial sums ----------------
__global__ void crop_kernel(CropP P) {
    int b = blockIdx.y;
    int pix = blockIdx.x * 256 + threadIdx.x;      // always < 50176
    int vrow = pix / IMGS, ucol = pix % IMGS;
    int x0 = g_crop[b*3+0], y0 = g_crop[b*3+1], s = g_crop[b*3+2];
    float sf = (float)s / (float)(IMGS - 1);
    float xs = (float)x0 + sf * (float)ucol;
    float ys = (float)y0 + sf * (float)vrow;
    xs = fminf(fmaxf(xs, 0.f), 255.f);
    ys = fminf(fmaxf(ys, 0.f), 255.f);
    float x0f = floorf(xs), y0f = floorf(ys);
    int xi = (int)x0f, yi = (int)y0f;
    float wx = xs - x0f, wy = ys - y0f;
    int x1 = min(xi + 1, 255), y1 = min(yi + 1, 255);
    float w00 = (1.f-wy)*(1.f-wx), w01 = (1.f-wy)*wx;
    float w10 = wy*(1.f-wx),       w11 = wy*wx;
    const float* xwb = g_xw + (size_t)b*3*HH*WW;
    float fb = P.fb[b];
    const float gw0 = 0.299f, gw1 = 0.587f, gw2 = 0.114f;
    float gray = 0.f;
    #pragma unroll
    for (int c = 0; c < 3; c++) {
        const float* img = xwb + c*HH*WW;
        float v = img[yi*WW + xi]*w00 + img[yi*WW + x1]*w01
                + img[y1*WW + xi]*w10 + img[y1*WW + x1]*w11;
        g_xc[(size_t)b*3*NPIX + c*NPIX + pix] = v;
        float yv = fminf(fmaxf(v * fb, 0.f), 1.f);
        gray += (c == 0 ? gw0 : (c == 1 ? gw1 : gw2)) * yv;
    }
    __shared__ float sred[256];
    sred[threadIdx.x] = gray;
    __syncthreads();
    for (int stride = 128; stride > 0; stride >>= 1) {
        if (threadIdx.x < stride) sred[threadIdx.x] += sred[threadIdx.x + stride];
        __syncthreads();
    }
    if (threadIdx.x == 0) g_partial[b*NBLK + blockIdx.x] = sred[0];
}

// ---------------- K3b: reduce partials -> mean ----------------
__global__ void mean_kernel() {
    int b = blockIdx.x, t = threadIdx.x;
    __shared__ float s[256];
    s[t] = (t < NBLK) ? g_partial[b*NBLK + t] : 0.f;
    __syncthreads();
    for (int stride = 128; stride > 0; stride >>= 1) {
        if (t < stride) s[t] += s[t + stride];
        __syncthreads();
    }
    if (t == 0) g_mean[b] = s[0] / (float)NPIX;
}

// ---------------- K4: color jitter ----------------
__global__ void jitter_kernel(JitP P) {
    int b = blockIdx.y;
    int pix = blockIdx.x * 256 + threadIdx.x;
    const float* xb = g_xc + (size_t)b*3*NPIX;
    float r0 = xb[pix], g0 = xb[NPIX + pix], b0 = xb[2*NPIX + pix];
    float fb = P.fb[b], fc = P.fc[b], fs = P.fs[b], fh = P.fhue[b];
    // brightness
    float r = fminf(fmaxf(r0*fb, 0.f), 1.f);
    float g = fminf(fmaxf(g0*fb, 0.f), 1.f);
    float bl = fminf(fmaxf(b0*fb, 0.f), 1.f);
    // contrast
    float mean = g_mean[b];
    r  = fminf(fmaxf(fc*r  + (1.f-fc)*mean, 0.f), 1.f);
    g  = fminf(fmaxf(fc*g  + (1.f-fc)*mean, 0.f), 1.f);
    bl = fminf(fmaxf(fc*bl + (1.f-fc)*mean, 0.f), 1.f);
    // saturation
    float gray = 0.299f*r + 0.587f*g + 0.114f*bl;
    r  = fminf(fmaxf(fs*r  + (1.f-fs)*gray, 0.f), 1.f);
    g  = fminf(fmaxf(fs*g  + (1.f-fs)*gray, 0.f), 1.f);
    bl = fminf(fmaxf(fs*bl + (1.f-fs)*gray, 0.f), 1.f);
    // rgb -> hsv
    float maxc = fmaxf(r, fmaxf(g, bl));
    float minc = fminf(r, fminf(g, bl));
    float d = maxc - minc;
    const float eps = 1e-8f;
    float s_ = d / fmaxf(maxc, eps);
    float dd = fmaxf(d, eps);
    float h;
    if (maxc == r) {
        float t = (g - bl) / dd;
        h = t - floorf(t / 6.f) * 6.f;   // floor-mod 6
    } else if (maxc == g) {
        h = (bl - r) / dd + 2.f;
    } else {
        h = (r - g) / dd + 4.f;
    }
    h = h / 6.f;
    if (d <= eps) h = 0.f;
    // hue shift + hsv -> rgb
    h += fh;
    float hm = h - floorf(h);
    float h6 = hm * 6.f;
    float fi = floorf(h6);
    float f = h6 - fi;
    float v = maxc;
    float p = v * (1.f - s_);
    float q = v * (1.f - s_*f);
    float t2 = v * (1.f - s_*(1.f - f));
    int i = ((int)fi) % 6;
    float rr, gg, bb;
    switch (i) {
        case 0:  rr = v;  gg = t2; bb = p;  break;
        case 1:  rr = q;  gg = v;  bb = p;  break;
        case 2:  rr = p;  gg = v;  bb = t2; break;
        case 3:  rr = p;  gg = q;  bb = v;  break;
        case 4:  rr = t2; gg = p;  bb = v;  break;
        default: rr = v;  gg = p;  bb = q;  break;
    }
    rr = fminf(fmaxf(rr, 0.f), 1.f);
    gg = fminf(fmaxf(gg, 0.f), 1.f);
    bb = fminf(fmaxf(bb, 0.f), 1.f);
    int ap = P.ap[b];
    float* ob = g_xj + (size_t)b*3*NPIX;
    ob[pix]          = ap ? rr : r0;
    ob[NPIX + pix]   = ap ? gg : g0;
    ob[2*NPIX + pix] = ap ? bb : b0;
}

// ---------------- K5: 3x9 gaussian blur (reflect pad) + final clip ----------------
__global__ void blur_kernel(BlurP P, float* __restrict__ out) {
    int b = blockIdx.y;
    int pix = blockIdx.x * 256 + threadIdx.x;
    int y = pix / IMGS, x = pix % IMGS;
    const float* xb = g_xj + (size_t)b*3*NPIX;
    int ap = P.ap[b];
    int sy[3], sx[9];
    #pragma unroll
    for (int dy = 0; dy < 3; dy++) {
        int t = y + dy - 1;
        sy[dy] = (t < 0) ? -t : ((t > IMGS-1) ? 2*(IMGS-1) - t : t);
    }
    #pragma unroll
    for (int dx = 0; dx < 9; dx++) {
        int t = x + dx - 4;
        sx[dx] = (t < 0) ? -t : ((t > IMGS-1) ? 2*(IMGS-1) - t : t);
    }
    float kyv[3], kxv[9];
    #pragma unroll
    for (int dy = 0; dy < 3; dy++) kyv[dy] = P.ky[b][dy];
    #pragma unroll
    for (int dx = 0; dx < 9; dx++) kxv[dx] = P.kx[b][dx];
    #pragma unroll
    for (int c = 0; c < 3; c++) {
        const float* img = xb + c*NPIX;
        float acc = 0.f;
        #pragma unroll
        for (int dy = 0; dy < 3; dy++) {
            const float* row = img + sy[dy]*IMGS;
            float ra = 0.f;
            #pragma unroll
            for (int dx = 0; dx < 9; dx++) ra += kxv[dx] * row[sx[dx]];
            acc += kyv[dy] * ra;
        }
        float base = img[pix];
        float o = ap ? acc : base;
        o = fminf(fmaxf(o, 0.f), 1.f);
        out[(size_t)b*3*NPIX + c*NPIX + pix] = o;
    }
}

// ============================================================================
// Host: JAX threefry2x32 (partitionable mode, the modern default)
// ============================================================================
static inline uint32_t rotl32(uint32_t v, int s) { return (v << s) | (v >> (32 - s)); }

static void tf2x32(uint32_t k0, uint32_t k1, uint32_t x0, uint32_t x1,
                   uint32_t* o0, uint32_t* o1) {
    uint32_t ks2 = k0 ^ k1 ^ 0x1BD11BDAu;
    x0 += k0; x1 += k1;
    static const int R[2][4] = {{13,15,26,6},{17,29,16,24}};
    const uint32_t inj0[5] = {k1, ks2, k0, k1, ks2};
    const uint32_t inj1[5] = {ks2, k0, k1, ks2, k0};
    for (int g = 0; g < 5; g++) {
        for (int r = 0; r < 4; r++) {
            x0 += x1; x1 = rotl32(x1, R[g & 1][r]); x1 ^= x0;
        }
        x0 += inj0[g];
        x1 += inj1[g] + (uint32_t)(g + 1);
    }
    *o0 = x0; *o1 = x1;
}

// partitionable random_bits (32-bit): counter = (hi=0, lo=i), bits = o0 ^ o1
static float h_u01(uint32_t k0, uint32_t k1, uint32_t i) {
    uint32_t a, b;
    tf2x32(k0, k1, 0u, i, &a, &b);
    uint32_t bits = a ^ b;
    uint32_t fbits = (bits >> 9) | 0x3f800000u;
    float f;
    memcpy(&f, &fbits, 4);
    return f - 1.0f;
}
static float h_uni(uint32_t k0, uint32_t k1, uint32_t i, float mn, float mx) {
    float u = h_u01(k0, k1, i);
    float v = u * (mx - mn) + mn;
    return (v < mn) ? mn : v;
}
// partitionable split: key_i = threefry(key, (0, i))
static void h_split(uint32_t k0, uint32_t k1, int n, uint32_t out[][2]) {
    for (int i = 0; i < n; i++)
        tf2x32(k0, k1, 0u, (uint32_t)i, &out[i][0], &out[i][1]);
}

extern "C" void kernel_launch(void* const* d_in, const int* in_sizes, int n_in,
                              void* d_out, int out_size) {
    const float* x = (const float*)d_in[0];
    float* out = (float*)d_out;
    const float PI_F = 3.14159265358979323846f;

    // key(42) -> (0, 42); split into kg, kc, kb
    uint32_t K3_[3][2];
    h_split(0u, 42u, 3, K3_);

    // ---- affine params ----
    uint32_t ka[6][2];
    h_split(K3_[0][0], K3_[0][1], 6, ka);
    static WarpP wp;
    for (int b = 0; b < BB; b++) {
        bool fh = h_u01(ka[0][0], ka[0][1], b) < 0.5f;
        bool fv = h_u01(ka[1][0], ka[1][1], b) < 0.5f;
        float ang = h_uni(ka[2][0], ka[2][1], b, -20.f, 20.f) * (PI_F / 180.f);
        float sc  = h_uni(ka[3][0], ka[3][1], b, 0.85f, 1.15f);
        float tx  = h_uni(ka[4][0], ka[4][1], b, -0.1f, 0.1f) * 256.f;
        float ty  = h_uni(ka[5][0], ka[5][1], b, -0.1f, 0.1f) * 256.f;
        float ca = cosf(ang) * sc, sa = sinf(ang) * sc;
        float a = ca, b2 = -sa, c2 = sa, d = ca;
        float cx = 127.5f, cy = 127.5f;
        float m02 = tx + cx - a*cx - b2*cy;
        float m12 = ty + cy - c2*cx - d*cy;
        float fxs = fh ? -1.f : 1.f, fys = fv ? -1.f : 1.f;
        float F02 = fh ? 255.f : 0.f, F12 = fv ? 255.f : 0.f;
        float M00 = a*fxs,  M01 = b2*fys, M02 = a*F02 + b2*F12 + m02;
        float M10 = c2*fxs, M11 = d*fys,  M12 = c2*F02 + d*F12 + m12;
        double det = (double)M00*(double)M11 - (double)M01*(double)M10;
        wp.inv[b][0] = (float)( (double)M11 / det);
        wp.inv[b][1] = (float)(-(double)M01 / det);
        wp.inv[b][2] = (float)(((double)M01*(double)M12 - (double)M02*(double)M11) / det);
        wp.inv[b][3] = (float)(-(double)M10 / det);
        wp.inv[b][4] = (float)( (double)M00 / det);
        wp.inv[b][5] = (float)(((double)M02*(double)M10 - (double)M00*(double)M12) / det);
    }

    // ---- color jitter params ----
    uint32_t kc5[5][2];
    h_split(K3_[1][0], K3_[1][1], 5, kc5);
    static CropP cp;
    static JitP jp;
    for (int b = 0; b < BB; b++) {
        float fb = h_uni(kc5[0][0], kc5[0][1], b, 0.7f, 1.3f);
        cp.fb[b] = fb; jp.fb[b] = fb;
        jp.fc[b]   = h_uni(kc5[1][0], kc5[1][1], b, 0.7f, 1.3f);
        jp.fs[b]   = h_uni(kc5[2][0], kc5[2][1], b, 0.7f, 1.3f);
        jp.fhue[b] = h_uni(kc5[3][0], kc5[3][1], b, -0.15f, 0.15f);
        jp.ap[b]   = (h_u01(kc5[4][0], kc5[4][1], b) < 0.7f) ? 1 : 0;
    }

    // ---- blur params ----
    uint32_t kb2[2][2];
    h_split(K3_[2][0], K3_[2][1], 2, kb2);
    static BlurP bp;
    for (int b = 0; b < BB; b++) {
        float sig = h_uni(kb2[0][0], kb2[0][1], b, 0.1f, 2.0f);
        float s2 = 2.f * sig * sig;
        float wy[3], wxv[9];
        float sumy = 0.f, sumx = 0.f;
        for (int i = 0; i < 3; i++) {
            float xk = (float)i - 1.f;
            wy[i] = expf(-(xk*xk) / s2);
            sumy += wy[i];
        }
        for (int i = 0; i < 9; i++) {
            float xk = (float)i - 4.f;
            wxv[i] = expf(-(xk*xk) / s2);
            sumx += wxv[i];
        }
        for (int i = 0; i < 3; i++) bp.ky[b][i] = wy[i] / sumy;
        for (int i = 0; i < 9; i++) bp.kx[b][i] = wxv[i] / sumx;
        bp.ap[b] = (h_u01(kb2[1][0], kb2[1][1], b) < 0.5f) ? 1 : 0;
    }

    // ---- launches (default stream, graph-capturable) ----
    warp_kernel<<<(BB*HH*WW + 255) / 256, 256>>>(x, wp);
    maxsq_kernel<<<BB, 256>>>();
    dim3 g3(NBLK, BB);
    crop_kernel<<<g3, 256>>>(cp);
    mean_kernel<<<BB, 256>>>();
    jitter_kernel<<<g3, 256>>>(jp);
    blur_kernel<<<g3, 256>>>(bp, out);
}

// round 4
// speedup vs baseline: 1.7887x; 1.7887x over previous
#include <cuda_runtime.h>
#include <cstdint>
#include <cstring>
#include <cmath>

#define BB 64
#define HH 256
#define WW 256
#define IMGS 224
#define NPIX (IMGS*IMGS)   /* 50176 */
#define NBLK 196           /* 50176 / 256 */
#define WARPBLKS 16384     /* BB*HH*WW / 256 */

// ---------------- device scratch (static globals; no allocs) ----------------
__device__ float g_xw[BB*3*HH*WW];     // warped 256x256
__device__ float g_xc[BB*3*NPIX];      // cropped 224x224
__device__ float g_partial[BB*NBLK];   // gray partial sums
__device__ int   g_crop[BB*3];         // x0,y0,s per batch

// ---------------- parameter structs (passed by value) ----------------
struct WarpP { float inv[BB][6]; };
struct CropP { float fb[BB]; };
struct JitP  { float fb[BB], fc[BB], fs[BB], fhue[BB]; int ap[BB]; };
struct BlurP { float ky[BB][3]; float kx[BB][9]; int ap[BB]; };

// ============================================================================
// K1: fused affine-warp (blocks >= 64) + per-batch max-square DP (blocks 0..63)
// ============================================================================
__device__ __forceinline__ int coverage_ok(const float* m, float fx, float fy) {
    float sx = m[0]*fx + m[1]*fy + m[2];
    float sy = m[3]*fx + m[4]*fy + m[5];
    float x0f = floorf(sx), y0f = floorf(sy);
    int xi = (int)x0f, yi = (int)y0f;
    float wx = sx - x0f, wy = sy - y0f;
    float i00 = (yi   >= 0 && yi   < HH && xi   >= 0 && xi   < WW) ? 1.f : 0.f;
    float i01 = (yi   >= 0 && yi   < HH && xi+1 >= 0 && xi+1 < WW) ? 1.f : 0.f;
    float i10 = (yi+1 >= 0 && yi+1 < HH && xi   >= 0 && xi   < WW) ? 1.f : 0.f;
    float i11 = (yi+1 >= 0 && yi+1 < HH && xi+1 >= 0 && xi+1 < WW) ? 1.f : 0.f;
    float cov = i00*(1.f-wy)*(1.f-wx) + i01*(1.f-wy)*wx + i10*wy*(1.f-wx) + i11*wy*wx;
    return cov > 0.5f ? 1 : 0;
}

__global__ void __launch_bounds__(256) warp_maxsq_kernel(const float* __restrict__ x, WarpP P) {
    __shared__ int s_wmin[8];
    __shared__ int s_bnd[2][8];
    __shared__ int s_v[256], s_i[256];

    if (blockIdx.x < BB) {
        // -------- maxsq role: one block per batch image --------
        int b = blockIdx.x;
        int j = threadIdx.x;
        int lane = j & 31, wd = j >> 5;
        const float* m = P.inv[b];
        float fx = (float)j;
        int prev = 0;
        int bestv = 0, besti = 0;
        int allm = 1;
        if (j < 8) s_bnd[0][j] = 0;
        __syncthreads();
        int p = 0;
        for (int i = 0; i < HH; i++) {
            int mk = coverage_ok(m, fx, (float)i);
            allm &= mk;
            int pls = __shfl_up_sync(0xffffffffu, prev, 1);
            int pl = (lane == 0) ? ((wd > 0) ? s_bnd[p][wd-1] : 0) : pls;
            int bj = min(prev, pl) + 1;
            int v = (mk ? bj : 0) - j;
            // inclusive warp prefix-min
            int xv = v;
            #pragma unroll
            for (int o = 1; o < 32; o <<= 1) {
                int y = __shfl_up_sync(0xffffffffu, xv, o);
                if (lane >= o) xv = min(xv, y);
            }
            if (lane == 31) s_wmin[wd] = xv;
            __syncthreads();
            int off = 0x7fffffff;
            #pragma unroll
            for (int t = 0; t < 7; t++) {
                int wv = s_wmin[t];
                if (t < wd) off = min(off, wv);
            }
            int pm = min(xv, off);
            int dcur = min(j + 1, pm + j);
            prev = dcur;
            if (lane == 31) s_bnd[p ^ 1][wd] = dcur;
            if (dcur > bestv) { bestv = dcur; besti = (i << 8) | j; }
            p ^= 1;
            __syncthreads();
        }
        int full = __syncthreads_and(allm);
        s_v[j] = bestv; s_i[j] = besti;
        __syncthreads();
        for (int stride = 128; stride > 0; stride >>= 1) {
            if (j < stride) {
                int v2 = s_v[j+stride], i2 = s_i[j+stride];
                if (v2 > s_v[j] || (v2 == s_v[j] && i2 < s_i[j])) { s_v[j] = v2; s_i[j] = i2; }
            }
            __syncthreads();
        }
        if (j == 0) {
            int s = s_v[0], idx = s_i[0];
            int ii = idx >> 8, jj = idx & 255;
            int x0 = jj + 1 - s, y0 = ii + 1 - s;
            if (s == 0) { x0 = WW/2; y0 = HH/2; s = 1; }
            if (full)   { x0 = 0; y0 = 0; s = 256; }
            g_crop[b*3+0] = x0; g_crop[b*3+1] = y0; g_crop[b*3+2] = s;
        }
        return;
    }

    // -------- warp role --------
    int idx = (blockIdx.x - BB) * 256 + threadIdx.x;
    int b = idx >> 16;
    int pp = idx & 65535;
    int h = pp >> 8;
    int w = pp & 255;
    const float* m = P.inv[b];
    float fx = (float)w, fy = (float)h;
    float sx = m[0]*fx + m[1]*fy + m[2];
    float sy = m[3]*fx + m[4]*fy + m[5];
    float cxs = fminf(fmaxf(sx, 0.f), 255.f);
    float cys = fminf(fmaxf(sy, 0.f), 255.f);
    float cx0f = floorf(cxs), cy0f = floorf(cys);
    int cx0 = (int)cx0f, cy0 = (int)cy0f;
    float cwx = cxs - cx0f, cwy = cys - cy0f;
    int x1 = min(cx0 + 1, 255), y1 = min(cy0 + 1, 255);
    float w00 = (1.f-cwy)*(1.f-cwx), w01 = (1.f-cwy)*cwx;
    float w10 = cwy*(1.f-cwx),       w11 = cwy*cwx;
    const float* xb = x + (size_t)b*3*HH*WW;
    float* ob = g_xw + (size_t)b*3*HH*WW;
    #pragma unroll
    for (int c = 0; c < 3; c++) {
        const float* img = xb + c*HH*WW;
        float v = __ldg(img + cy0*WW + cx0)*w00 + __ldg(img + cy0*WW + x1)*w01
                + __ldg(img + y1*WW + cx0)*w10  + __ldg(img + y1*WW + x1)*w11;
        ob[c*HH*WW + h*WW + w] = v;
    }
}

// ============================================================================
// K2: crop resample + brightness-gray partial sums
// ============================================================================
__global__ void __launch_bounds__(256) crop_kernel(CropP P) {
    int b = blockIdx.y;
    int pix = blockIdx.x * 256 + threadIdx.x;
    int vrow = pix / IMGS, ucol = pix % IMGS;
    int x0 = g_crop[b*3+0], y0 = g_crop[b*3+1], s = g_crop[b*3+2];
    float sf = (float)s / (float)(IMGS - 1);
    float xs = (float)x0 + sf * (float)ucol;
    float ys = (float)y0 + sf * (float)vrow;
    xs = fminf(fmaxf(xs, 0.f), 255.f);
    ys = fminf(fmaxf(ys, 0.f), 255.f);
    float x0f = floorf(xs), y0f = floorf(ys);
    int xi = (int)x0f, yi = (int)y0f;
    float wx = xs - x0f, wy = ys - y0f;
    int x1 = min(xi + 1, 255), y1 = min(yi + 1, 255);
    float w00 = (1.f-wy)*(1.f-wx), w01 = (1.f-wy)*wx;
    float w10 = wy*(1.f-wx),       w11 = wy*wx;
    const float* xwb = g_xw + (size_t)b*3*HH*WW;
    float fb = P.fb[b];
    float gray = 0.f;
    #pragma unroll
    for (int c = 0; c < 3; c++) {
        const float* img = xwb + c*HH*WW;
        float v = __ldg(img + yi*WW + xi)*w00 + __ldg(img + yi*WW + x1)*w01
                + __ldg(img + y1*WW + xi)*w10 + __ldg(img + y1*WW + x1)*w11;
        g_xc[(size_t)b*3*NPIX + c*NPIX + pix] = v;
        float yv = fminf(fmaxf(v * fb, 0.f), 1.f);
        gray += (c == 0 ? 0.299f : (c == 1 ? 0.587f : 0.114f)) * yv;
    }
    __shared__ float sred[256];
    sred[threadIdx.x] = gray;
    __syncthreads();
    for (int stride = 128; stride > 0; stride >>= 1) {
        if (threadIdx.x < stride) sred[threadIdx.x] += sred[threadIdx.x + stride];
        __syncthreads();
    }
    if (threadIdx.x == 0) g_partial[b*NBLK + blockIdx.x] = sred[0];
}

// ============================================================================
// K3: fused mean-reduce + color jitter + 3x9 blur + clip   (tiled)
// ============================================================================
__device__ __forceinline__ void jitter_px(float r0, float g0, float b0,
                                          float fb, float fc, float fs, float fh,
                                          float mean, int ap,
                                          float& ro, float& go, float& bo) {
    if (!ap) { ro = r0; go = g0; bo = b0; return; }
    float r = fminf(fmaxf(r0*fb, 0.f), 1.f);
    float g = fminf(fmaxf(g0*fb, 0.f), 1.f);
    float bl = fminf(fmaxf(b0*fb, 0.f), 1.f);
    r  = fminf(fmaxf(fc*r  + (1.f-fc)*mean, 0.f), 1.f);
    g  = fminf(fmaxf(fc*g  + (1.f-fc)*mean, 0.f), 1.f);
    bl = fminf(fmaxf(fc*bl + (1.f-fc)*mean, 0.f), 1.f);
    float gray = 0.299f*r + 0.587f*g + 0.114f*bl;
    r  = fminf(fmaxf(fs*r  + (1.f-fs)*gray, 0.f), 1.f);
    g  = fminf(fmaxf(fs*g  + (1.f-fs)*gray, 0.f), 1.f);
    bl = fminf(fmaxf(fs*bl + (1.f-fs)*gray, 0.f), 1.f);
    float maxc = fmaxf(r, fmaxf(g, bl));
    float minc = fminf(r, fminf(g, bl));
    float d = maxc - minc;
    const float eps = 1e-8f;
    float s_ = d / fmaxf(maxc, eps);
    float dd = fmaxf(d, eps);
    float h;
    if (maxc == r) {
        float t = (g - bl) / dd;
        h = t - floorf(t / 6.f) * 6.f;
    } else if (maxc == g) {
        h = (bl - r) / dd + 2.f;
    } else {
        h = (r - g) / dd + 4.f;
    }
    h = h / 6.f;
    if (d <= eps) h = 0.f;
    h += fh;
    float hm = h - floorf(h);
    float h6 = hm * 6.f;
    float fi = floorf(h6);
    float f = h6 - fi;
    float v = maxc;
    float pq = v * (1.f - s_);
    float q = v * (1.f - s_*f);
    float t2 = v * (1.f - s_*(1.f - f));
    int i = ((int)fi) % 6;
    float rr, gg, bb;
    switch (i) {
        case 0:  rr = v;  gg = t2; bb = pq; break;
        case 1:  rr = q;  gg = v;  bb = pq; break;
        case 2:  rr = pq; gg = v;  bb = t2; break;
        case 3:  rr = pq; gg = q;  bb = v;  break;
        case 4:  rr = t2; gg = pq; bb = v;  break;
        default: rr = v;  gg = pq; bb = q;  break;
    }
    ro = fminf(fmaxf(rr, 0.f), 1.f);
    go = fminf(fmaxf(gg, 0.f), 1.f);
    bo = fminf(fmaxf(bb, 0.f), 1.f);
}

#define TILE_H 8
#define HALO_H (TILE_H + 2)
#define HALO_W (IMGS + 8)   /* 232 */

__global__ void __launch_bounds__(256) jb_kernel(JitP jp, BlurP bp, float* __restrict__ out) {
    int b = blockIdx.y;
    int ty0 = blockIdx.x * TILE_H;
    int tid = threadIdx.x;
    __shared__ float tile[3][HALO_H][HALO_W];
    __shared__ float red[256];

    // mean reduce (per-block, reads 196 partials from L2)
    red[tid] = (tid < NBLK) ? g_partial[b*NBLK + tid] : 0.f;
    __syncthreads();
    for (int stride = 128; stride > 0; stride >>= 1) {
        if (tid < stride) red[tid] += red[tid + stride];
        __syncthreads();
    }
    float mean = red[0] / (float)NPIX;
    __syncthreads();

    float fb = jp.fb[b], fc = jp.fc[b], fs = jp.fs[b], fh = jp.fhue[b];
    int apj = jp.ap[b];
    const float* xb = g_xc + (size_t)b*3*NPIX;

    // load halo + jitter into smem
    for (int k = tid; k < HALO_H*HALO_W; k += 256) {
        int hr = k / HALO_W, hc = k % HALO_W;
        int gy = ty0 + hr - 1;
        gy = (gy < 0) ? -gy : ((gy > IMGS-1) ? 2*(IMGS-1) - gy : gy);
        int gx = hc - 4;
        gx = (gx < 0) ? -gx : ((gx > IMGS-1) ? 2*(IMGS-1) - gx : gx);
        int pix = gy*IMGS + gx;
        float r0 = __ldg(xb + pix);
        float g0 = __ldg(xb + NPIX + pix);
        float b0 = __ldg(xb + 2*NPIX + pix);
        float ro, go, bo;
        jitter_px(r0, g0, b0, fb, fc, fs, fh, mean, apj, ro, go, bo);
        tile[0][hr][hc] = ro;
        tile[1][hr][hc] = go;
        tile[2][hr][hc] = bo;
    }
    __syncthreads();

    int apb = bp.ap[b];
    float kyv[3], kxv[9];
    #pragma unroll
    for (int i = 0; i < 3; i++) kyv[i] = bp.ky[b][i];
    #pragma unroll
    for (int i = 0; i < 9; i++) kxv[i] = bp.kx[b][i];

    for (int t = tid; t < TILE_H*IMGS; t += 256) {
        int r = t / IMGS, c = t % IMGS;
        #pragma unroll
        for (int ch = 0; ch < 3; ch++) {
            float acc = 0.f;
            #pragma unroll
            for (int dy = 0; dy < 3; dy++) {
                float ra = 0.f;
                #pragma unroll
                for (int dx = 0; dx < 9; dx++) ra += kxv[dx] * tile[ch][r+dy][c+dx];
                acc += kyv[dy] * ra;
            }
            float base = tile[ch][r+1][c+4];
            float o = apb ? acc : base;
            o = fminf(fmaxf(o, 0.f), 1.f);
            out[(size_t)b*3*NPIX + ch*NPIX + (ty0+r)*IMGS + c] = o;
        }
    }
}

// ============================================================================
// Host: JAX threefry2x32 (partitionable mode)
// ============================================================================
static inline uint32_t rotl32(uint32_t v, int s) { return (v << s) | (v >> (32 - s)); }

static void tf2x32(uint32_t k0, uint32_t k1, uint32_t x0, uint32_t x1,
                   uint32_t* o0, uint32_t* o1) {
    uint32_t ks2 = k0 ^ k1 ^ 0x1BD11BDAu;
    x0 += k0; x1 += k1;
    static const int R[2][4] = {{13,15,26,6},{17,29,16,24}};
    const uint32_t inj0[5] = {k1, ks2, k0, k1, ks2};
    const uint32_t inj1[5] = {ks2, k0, k1, ks2, k0};
    for (int g = 0; g < 5; g++) {
        for (int r = 0; r < 4; r++) {
            x0 += x1; x1 = rotl32(x1, R[g & 1][r]); x1 ^= x0;
        }
        x0 += inj0[g];
        x1 += inj1[g] + (uint32_t)(g + 1);
    }
    *o0 = x0; *o1 = x1;
}

static float h_u01(uint32_t k0, uint32_t k1, uint32_t i) {
    uint32_t a, b;
    tf2x32(k0, k1, 0u, i, &a, &b);
    uint32_t bits = a ^ b;
    uint32_t fbits = (bits >> 9) | 0x3f800000u;
    float f;
    memcpy(&f, &fbits, 4);
    return f - 1.0f;
}
static float h_uni(uint32_t k0, uint32_t k1, uint32_t i, float mn, float mx) {
    float u = h_u01(k0, k1, i);
    float v = u * (mx - mn) + mn;
    return (v < mn) ? mn : v;
}
static void h_split(uint32_t k0, uint32_t k1, int n, uint32_t out[][2]) {
    for (int i = 0; i < n; i++)
        tf2x32(k0, k1, 0u, (uint32_t)i, &out[i][0], &out[i][1]);
}

extern "C" void kernel_launch(void* const* d_in, const int* in_sizes, int n_in,
                              void* d_out, int out_size) {
    const float* x = (const float*)d_in[0];
    float* out = (float*)d_out;
    const float PI_F = 3.14159265358979323846f;

    uint32_t K3_[3][2];
    h_split(0u, 42u, 3, K3_);

    // ---- affine params ----
    uint32_t ka[6][2];
    h_split(K3_[0][0], K3_[0][1], 6, ka);
    static WarpP wp;
    for (int b = 0; b < BB; b++) {
        bool fhl = h_u01(ka[0][0], ka[0][1], b) < 0.5f;
        bool fvl = h_u01(ka[1][0], ka[1][1], b) < 0.5f;
        float ang = h_uni(ka[2][0], ka[2][1], b, -20.f, 20.f) * (PI_F / 180.f);
        float sc  = h_uni(ka[3][0], ka[3][1], b, 0.85f, 1.15f);
        float tx  = h_uni(ka[4][0], ka[4][1], b, -0.1f, 0.1f) * 256.f;
        float ty  = h_uni(ka[5][0], ka[5][1], b, -0.1f, 0.1f) * 256.f;
        float ca = cosf(ang) * sc, sa = sinf(ang) * sc;
        float a = ca, b2 = -sa, c2 = sa, d = ca;
        float cx = 127.5f, cy = 127.5f;
        float m02 = tx + cx - a*cx - b2*cy;
        float m12 = ty + cy - c2*cx - d*cy;
        float fxs = fhl ? -1.f : 1.f, fys = fvl ? -1.f : 1.f;
        float F02 = fhl ? 255.f : 0.f, F12 = fvl ? 255.f : 0.f;
        float M00 = a*fxs,  M01 = b2*fys, M02 = a*F02 + b2*F12 + m02;
        float M10 = c2*fxs, M11 = d*fys,  M12 = c2*F02 + d*F12 + m12;
        double det = (double)M00*(double)M11 - (double)M01*(double)M10;
        wp.inv[b][0] = (float)( (double)M11 / det);
        wp.inv[b][1] = (float)(-(double)M01 / det);
        wp.inv[b][2] = (float)(((double)M01*(double)M12 - (double)M02*(double)M11) / det);
        wp.inv[b][3] = (float)(-(double)M10 / det);
        wp.inv[b][4] = (float)( (double)M00 / det);
        wp.inv[b][5] = (float)(((double)M02*(double)M10 - (double)M00*(double)M12) / det);
    }

    // ---- color jitter params ----
    uint32_t kc5[5][2];
    h_split(K3_[1][0], K3_[1][1], 5, kc5);
    static CropP cp;
    static JitP jp;
    for (int b = 0; b < BB; b++) {
        float fb = h_uni(kc5[0][0], kc5[0][1], b, 0.7f, 1.3f);
        cp.fb[b] = fb; jp.fb[b] = fb;
        jp.fc[b]   = h_uni(kc5[1][0], kc5[1][1], b, 0.7f, 1.3f);
        jp.fs[b]   = h_uni(kc5[2][0], kc5[2][1], b, 0.7f, 1.3f);
        jp.fhue[b] = h_uni(kc5[3][0], kc5[3][1], b, -0.15f, 0.15f);
        jp.ap[b]   = (h_u01(kc5[4][0], kc5[4][1], b) < 0.7f) ? 1 : 0;
    }

    // ---- blur params ----
    uint32_t kb2[2][2];
    h_split(K3_[2][0], K3_[2][1], 2, kb2);
    static BlurP bp;
    for (int b = 0; b < BB; b++) {
        float sig = h_uni(kb2[0][0], kb2[0][1], b, 0.1f, 2.0f);
        float s2 = 2.f * sig * sig;
        float wy[3], wxv[9];
        float sumy = 0.f, sumx = 0.f;
        for (int i = 0; i < 3; i++) {
            float xk = (float)i - 1.f;
            wy[i] = expf(-(xk*xk) / s2);
            sumy += wy[i];
        }
        for (int i = 0; i < 9; i++) {
            float xk = (float)i - 4.f;
            wxv[i] = expf(-(xk*xk) / s2);
            sumx += wxv[i];
        }
        for (int i = 0; i < 3; i++) bp.ky[b][i] = wy[i] / sumy;
        for (int i = 0; i < 9; i++) bp.kx[b][i] = wxv[i] / sumx;
        bp.ap[b] = (h_u01(kb2[1][0], kb2[1][1], b) < 0.5f) ? 1 : 0;
    }

    // ---- launches ----
    warp_maxsq_kernel<<<BB + WARPBLKS, 256>>>(x, wp);
    dim3 g3(NBLK, BB);
    crop_kernel<<<g3, 256>>>(cp);
    dim3 g4(IMGS / TILE_H, BB);
    jb_kernel<<<g4, 256>>>(jp, bp, out);
}